// round 9
// baseline (speedup 1.0000x reference)
#include <cuda_runtime.h>
#include <cuda_bf16.h>
#include <math.h>
#include <stdint.h>

// Inter-layer scratch + sync (allocation-free rule: __device__ globals).
__device__ float g_out0[729];
__device__ float g_out1[27];
__device__ float g_uR0[729 * 32];     // backward half-results, layer 0
__device__ float g_uR1[27 * 32];      // backward half-results, layer 1
__device__ unsigned g_half0[729];     // layer0 backward-half done flags
__device__ unsigned g_grp[27];        // per-layer1-chain producer counters
__device__ unsigned g_half1[27];      // layer1 backward-half done flags
__device__ unsigned g_ctr1;           // layer1 completion counter

#define PI_HALF 1.57079632679489662f
#define STAGE_FLOATS 2048
#define FWD_STAGES 13                  // stages 0..12  (sites 1..13)
// backward: stages 24..13 (sites 25..14)

// ---------------- helpers ----------------
__device__ __forceinline__ float warp_sum(float v) {
#pragma unroll
    for (int o = 16; o > 0; o >>= 1)
        v += __shfl_down_sync(0xffffffffu, v, o);
    return v;
}
__device__ __forceinline__ void l2_prefetch_line(const float* p) {
    asm volatile("prefetch.global.L2 [%0];" :: "l"(p));
}
__device__ __forceinline__ void spin_until(const unsigned* c, unsigned target) {
    unsigned v;
    do {
        asm volatile("ld.global.acquire.gpu.u32 %0, [%1];"
                     : "=r"(v) : "l"(c) : "memory");
        if (v >= target) return;
        __nanosleep(128);
    } while (true);
}
// Coalesced column load + cos/sin combine: mval[d] = c*A[d][0][t] + s*A[d][1][t]
__device__ __forceinline__ void load_mval(float (&mval)[32],
                                          const float* __restrict__ g,
                                          int t, float c, float s) {
#pragma unroll
    for (int d = 0; d < 32; d++) {
        const float a0 = __ldcs(g + d * 64 + t);
        const float a1 = __ldcs(g + d * 64 + 32 + t);
        mval[d] = fmaf(a0, c, a1 * s);
    }
}
// Forward step (row-vector): v_new[t] = sum_d v[d] * M[d][t]
__device__ __forceinline__ float step_fwd(const float (&mval)[32], float v) {
    float acc = 0.0f;
#pragma unroll
    for (int d = 0; d < 32; d++)
        acc = fmaf(__shfl_sync(0xffffffffu, v, d), mval[d], acc);
    return acc;
}
// Backward step (column-vector): u_new[d] = sum_e M[d][e] * u[e].
// Lane t holds column t (mval) and u[t]; per-row butterfly reduction.
__device__ __forceinline__ float step_bwd(const float (&mval)[32], float u, int t) {
    float unew = 0.0f;
#pragma unroll
    for (int d = 0; d < 32; d++) {
        float r = mval[d] * u;
#pragma unroll
        for (int o = 16; o > 0; o >>= 1)
            r += __shfl_xor_sync(0xffffffffu, r, o);
        if (t == d) unew = r;
    }
    return unew;
}

// Forward half-chain: first-embed + stages 0..12. Returns v (lane t = comp t).
__device__ __forceinline__ float half_fwd(const float* __restrict__ mid,
                                          const float* __restrict__ first,
                                          const float* sc, const float* ss, int t) {
    float v = fmaf(first[t], sc[0], first[32 + t] * ss[0]);
    float mval[32];
#pragma unroll 1
    for (int m = 0; m < FWD_STAGES; m++) {
        load_mval(mval, mid + m * STAGE_FLOATS, t, sc[m + 1], ss[m + 1]);
        v = step_fwd(mval, v);
    }
    return v;
}
// Backward half-chain: last-embed + stages 24..13. Returns u (lane t = comp t).
__device__ __forceinline__ float half_bwd(const float* __restrict__ mid,
                                          const float* __restrict__ last,
                                          const float* sc, const float* ss, int t) {
    float u = fmaf(last[2 * t], sc[26], last[2 * t + 1] * ss[26]);
    float mval[32];
#pragma unroll 1
    for (int m = 24; m >= FWD_STAGES; m--) {
        load_mval(mval, mid + m * STAGE_FLOATS, t, sc[m + 1], ss[m + 1]);
        u = step_bwd(mval, u, t);
    }
    return u;
}

__global__ void reset_kernel() {
    const int i = threadIdx.x;
    if (i < 729) g_half0[i] = 0;
    if (i < 27) { g_grp[i] = 0; g_half1[i] = 0; }
    if (i == 0) g_ctr1 = 0;
}

// 1458 blocks x 32 threads.
//   bid <  729 : forward half of layer0 chain n=bid, then combine; n<27 also layer1 fwd.
//   bid >= 729 : backward half of layer0 chain n=bid-729; n<27 also layer1 bwd.
//   bid == 0   : final layer.
__global__ void __launch_bounds__(32)
fused_kernel(const float* __restrict__ img,
             const float* __restrict__ l0f, const float* __restrict__ l0m,
             const float* __restrict__ l0l,
             const float* __restrict__ l1f, const float* __restrict__ l1m,
             const float* __restrict__ l1l,
             const float* __restrict__ ff,  const float* __restrict__ fm,
             const float* __restrict__ fl,
             float* __restrict__ out)
{
    __shared__ float sc[27], ss[27];
    const int bid = blockIdx.x;
    const int t = threadIdx.x;
    const bool fwd = (bid < 729);
    const int n = fwd ? bid : bid - 729;

    // Embedding of the 27 squeezed image sites (every block computes all 27).
    if (t < 27) {
        const int bh = n / 81, bv = (n / 9) % 9, bd = n % 9;
        const int x = t / 9, y = (t / 3) % 3, z = t % 3;
        const float val = img[(3 * bh + x) * 729 + (3 * bv + y) * 27 + (3 * bd + z)];
        float cv, sv;
        sincosf(PI_HALF * val, &sv, &cv);
        sc[t] = cv; ss[t] = sv;
    }
    __syncwarp();

    const float* gm0 = l0m + (long)n * (25 * STAGE_FLOATS);

    if (!fwd) {
        // ---------- Layer 0 backward half ----------
        const float u = half_bwd(gm0, l0l + n * 64, sc, ss, t);
        g_uR0[n * 32 + t] = u;
        __threadfence();
        if (t == 0) atomicAdd(&g_half0[n], 1u);
        if (n >= 27) return;

        // ---------- Layer 1 backward half (chains 0..26) ----------
        const float* gm1 = l1m + n * (25 * STAGE_FLOATS);
        // L2-warm my 12 stages before spinning.
        for (int i = t; i < (25 - FWD_STAGES) * STAGE_FLOATS / 32; i += 32)
            l2_prefetch_line(gm1 + FWD_STAGES * STAGE_FLOATS + i * 32);
        spin_until(&g_grp[n], 27u);

        __syncwarp();
        if (t < 27) {
            const int bh = n / 9, bv = (n / 3) % 3, bd = n % 3;
            const int x = t / 9, y = (t / 3) % 3, z = t % 3;
            const float val = __ldcg(&g_out0[(3 * bh + x) * 81 + (3 * bv + y) * 9 + (3 * bd + z)]);
            float cv, sv;
            sincosf(PI_HALF * val, &sv, &cv);
            sc[t] = cv; ss[t] = sv;
        }
        __syncwarp();

        const float u1 = half_bwd(gm1, l1l + n * 64, sc, ss, t);
        g_uR1[n * 32 + t] = u1;
        __threadfence();
        if (t == 0) atomicAdd(&g_half1[n], 1u);
        return;
    }

    // ---------- Layer 0 forward half + combine ----------
    float v = half_fwd(gm0, l0f + n * 64, sc, ss, t);
    spin_until(&g_half0[n], 1u);
    {
        const float uR = __ldcg(&g_uR0[n * 32 + t]);
        const float r = warp_sum(v * uR);
        if (t == 0) {
            g_out0[n] = r;
            __threadfence();
            const int X = n / 81, Y = (n / 9) % 9, Z = n % 9;
            atomicAdd(&g_grp[(X / 3) * 9 + (Y / 3) * 3 + (Z / 3)], 1u);
        }
    }
    if (n >= 27) return;

    // ---------- Layer 1 forward half + combine (chains 0..26) ----------
    const float* gm1 = l1m + n * (25 * STAGE_FLOATS);
    for (int i = t; i < FWD_STAGES * STAGE_FLOATS / 32; i += 32)
        l2_prefetch_line(gm1 + i * 32);
    if (n == 0) {                                 // final-layer weights too
        for (int i = t; i < 25 * STAGE_FLOATS / 32; i += 32)
            l2_prefetch_line(fm + i * 32);
    }
    spin_until(&g_grp[n], 27u);

    __syncwarp();
    if (t < 27) {
        const int bh = n / 9, bv = (n / 3) % 3, bd = n % 3;
        const int x = t / 9, y = (t / 3) % 3, z = t % 3;
        const float val = __ldcg(&g_out0[(3 * bh + x) * 81 + (3 * bv + y) * 9 + (3 * bd + z)]);
        float cv, sv;
        sincosf(PI_HALF * val, &sv, &cv);
        sc[t] = cv; ss[t] = sv;
    }
    __syncwarp();

    v = half_fwd(gm1, l1f + n * 64, sc, ss, t);
    spin_until(&g_half1[n], 1u);
    {
        const float uR = __ldcg(&g_uR1[n * 32 + t]);
        const float r = warp_sum(v * uR);
        if (t == 0) {
            g_out1[n] = r;
            __threadfence();
            atomicAdd(&g_ctr1, 1u);
        }
    }
    if (n != 0) return;

    // ---------- Final layer (block 0): full backward chain from L2 ----------
    spin_until(&g_ctr1, 27u);

    __syncwarp();
    if (t < 27) {
        // (3,3,3) squeeze of g_out1 is the identity permutation
        float cv, sv;
        sincosf(PI_HALF * __ldcg(&g_out1[t]), &sv, &cv);
        sc[t] = cv; ss[t] = sv;
    }
    __syncwarp();

    float u = fmaf(fl[2 * t], sc[26], fl[2 * t + 1] * ss[26]);
    float mval[32];
#pragma unroll 1
    for (int m = 24; m >= 0; m--) {
        load_mval(mval, fm + m * STAGE_FLOATS, t, sc[m + 1], ss[m + 1]);
        u = step_bwd(mval, u, t);
    }
#pragma unroll
    for (int o = 0; o < 10; o++) {
        float p = fmaf(ff[o * 32 + t], sc[0], ff[320 + o * 32 + t] * ss[0]) * u;
        p = warp_sum(p);
        if (t == 0) out[o] = p;
    }
}

extern "C" void kernel_launch(void* const* d_in, const int* in_sizes, int n_in,
                              void* d_out, int out_size)
{
    const float* img      = (const float*)d_in[0];
    const float* l0_first = (const float*)d_in[1];
    const float* l0_mid   = (const float*)d_in[2];
    const float* l0_last  = (const float*)d_in[3];
    const float* l1_first = (const float*)d_in[4];
    const float* l1_mid   = (const float*)d_in[5];
    const float* l1_last  = (const float*)d_in[6];
    const float* f_first  = (const float*)d_in[7];
    const float* f_mid    = (const float*)d_in[8];
    const float* f_last   = (const float*)d_in[9];
    float* out = (float*)d_out;

    reset_kernel<<<1, 1024>>>();
    fused_kernel<<<1458, 32>>>(img, l0_first, l0_mid, l0_last,
                               l1_first, l1_mid, l1_last,
                               f_first, f_mid, f_last, out);
}

// round 10
// speedup vs baseline: 1.3213x; 1.3213x over previous
#include <cuda_runtime.h>
#include <cuda_bf16.h>
#include <math.h>
#include <stdint.h>

// Inter-layer scratch + sync (allocation-free rule: __device__ globals).
__device__ float g_out0[729];
__device__ float g_out1[27];
__device__ float g_uR0[729 * 32];     // backward half-results, layer 0
__device__ float g_uR1[27 * 32];      // backward half-results, layer 1
__device__ unsigned g_half0[729];     // layer0 backward-half done flags
__device__ unsigned g_grp[27];        // per-layer1-chain producer counters
__device__ unsigned g_half1[27];      // layer1 backward-half done flags
__device__ unsigned g_ctr1;           // layer1 completion counter

#define PI_HALF 1.57079632679489662f
#define STAGE_FLOATS 2048
#define FWD_STAGES 13                  // fwd: stages 0..12; bwd: stages 24..13

// ---------------- helpers ----------------
__device__ __forceinline__ float warp_sum(float v) {
#pragma unroll
    for (int o = 16; o > 0; o >>= 1)
        v += __shfl_down_sync(0xffffffffu, v, o);
    return v;
}
__device__ __forceinline__ void l2_prefetch_line(const float* p) {
    asm volatile("prefetch.global.L2 [%0];" :: "l"(p));
}
__device__ __forceinline__ void spin_until(const unsigned* c, unsigned target) {
    unsigned v;
    do {
        asm volatile("ld.global.acquire.gpu.u32 %0, [%1];"
                     : "=r"(v) : "l"(c) : "memory");
        if (v >= target) return;
        __nanosleep(128);
    } while (true);
}

// ---------- forward step: coalesced column loads (lane = out bond e) ----------
__device__ __forceinline__ float step_fwd(const float* __restrict__ g, float v,
                                          int t, float c, float s) {
    float mval[32];
#pragma unroll
    for (int d = 0; d < 32; d++) {
        const float a0 = __ldcs(g + d * 64 + t);
        const float a1 = __ldcs(g + d * 64 + 32 + t);
        mval[d] = fmaf(a0, c, a1 * s);
    }
    float acc = 0.0f;
#pragma unroll
    for (int d = 0; d < 32; d++)
        acc = fmaf(__shfl_sync(0xffffffffu, v, d), mval[d], acc);
    return acc;
}

// ---------- backward step: per-lane contiguous ROW loads (lane = row d) ----------
// u_new[t] = sum_e (c*A[t][0][e] + s*A[t][1][e]) * u[e]
// Row = 64 contiguous floats at g + t*64 -> 16 independent LDG.128 per lane.
__device__ __forceinline__ float step_bwd(const float* __restrict__ g, float u,
                                          int t, float c, float s) {
    const float4* __restrict__ rp = (const float4*)(g + t * 64);
    float4 q[16];
#pragma unroll
    for (int i = 0; i < 16; i++)
        q[i] = __ldcs(rp + i);
    float acc0 = 0.0f, acc1 = 0.0f;
#pragma unroll
    for (int i = 0; i < 8; i++) {
        const float4 a = q[i];       // A[t][0][4i..4i+3]
        const float4 b = q[8 + i];   // A[t][1][4i..4i+3]
        float ue;
        ue = __shfl_sync(0xffffffffu, u, 4 * i + 0);
        acc0 = fmaf(a.x, ue, acc0);  acc1 = fmaf(b.x, ue, acc1);
        ue = __shfl_sync(0xffffffffu, u, 4 * i + 1);
        acc0 = fmaf(a.y, ue, acc0);  acc1 = fmaf(b.y, ue, acc1);
        ue = __shfl_sync(0xffffffffu, u, 4 * i + 2);
        acc0 = fmaf(a.z, ue, acc0);  acc1 = fmaf(b.z, ue, acc1);
        ue = __shfl_sync(0xffffffffu, u, 4 * i + 3);
        acc0 = fmaf(a.w, ue, acc0);  acc1 = fmaf(b.w, ue, acc1);
    }
    return fmaf(acc0, c, acc1 * s);
}

// Forward half-chain: first-embed + stages 0..12.
__device__ __forceinline__ float half_fwd(const float* __restrict__ mid,
                                          const float* __restrict__ first,
                                          const float* sc, const float* ss, int t) {
    float v = fmaf(first[t], sc[0], first[32 + t] * ss[0]);
#pragma unroll 1
    for (int m = 0; m < FWD_STAGES; m++)
        v = step_fwd(mid + m * STAGE_FLOATS, v, t, sc[m + 1], ss[m + 1]);
    return v;
}
// Backward half-chain: last-embed + stages 24..13.
__device__ __forceinline__ float half_bwd(const float* __restrict__ mid,
                                          const float* __restrict__ last,
                                          const float* sc, const float* ss, int t) {
    float u = fmaf(last[2 * t], sc[26], last[2 * t + 1] * ss[26]);
#pragma unroll 1
    for (int m = 24; m >= FWD_STAGES; m--)
        u = step_bwd(mid + m * STAGE_FLOATS, u, t, sc[m + 1], ss[m + 1]);
    return u;
}

__global__ void reset_kernel() {
    const int i = threadIdx.x;
    if (i < 729) g_half0[i] = 0;
    if (i < 27) { g_grp[i] = 0; g_half1[i] = 0; }
    if (i == 0) g_ctr1 = 0;
}

// 1458 blocks x 32 threads, all co-resident (regs*32*10 << regfile).
//   bid <  729 : forward half of layer0 chain n=bid, then combine; n<27 also layer1 fwd.
//   bid >= 729 : backward half of layer0 chain n=bid-729; n<27 also layer1 bwd.
//   bid == 0   : final layer.
__global__ void __launch_bounds__(32)
fused_kernel(const float* __restrict__ img,
             const float* __restrict__ l0f, const float* __restrict__ l0m,
             const float* __restrict__ l0l,
             const float* __restrict__ l1f, const float* __restrict__ l1m,
             const float* __restrict__ l1l,
             const float* __restrict__ ff,  const float* __restrict__ fm,
             const float* __restrict__ fl,
             float* __restrict__ out)
{
    __shared__ float sc[27], ss[27];
    const int bid = blockIdx.x;
    const int t = threadIdx.x;
    const bool fwd = (bid < 729);
    const int n = fwd ? bid : bid - 729;

    // Embedding of the 27 squeezed image sites.
    if (t < 27) {
        const int bh = n / 81, bv = (n / 9) % 9, bd = n % 9;
        const int x = t / 9, y = (t / 3) % 3, z = t % 3;
        const float val = img[(3 * bh + x) * 729 + (3 * bv + y) * 27 + (3 * bd + z)];
        float cv, sv;
        sincosf(PI_HALF * val, &sv, &cv);
        sc[t] = cv; ss[t] = sv;
    }
    __syncwarp();

    const float* gm0 = l0m + (long)n * (25 * STAGE_FLOATS);

    if (!fwd) {
        // ---------- Layer 0 backward half ----------
        const float u = half_bwd(gm0, l0l + n * 64, sc, ss, t);
        g_uR0[n * 32 + t] = u;
        __threadfence();
        if (t == 0) atomicAdd(&g_half0[n], 1u);
        if (n >= 27) return;

        // ---------- Layer 1 backward half (chains 0..26) ----------
        const float* gm1 = l1m + n * (25 * STAGE_FLOATS);
        // L2-warm my 12 stages before spinning.
        for (int i = t; i < (25 - FWD_STAGES) * STAGE_FLOATS / 32; i += 32)
            l2_prefetch_line(gm1 + FWD_STAGES * STAGE_FLOATS + i * 32);
        spin_until(&g_grp[n], 27u);

        __syncwarp();
        if (t < 27) {
            const int bh = n / 9, bv = (n / 3) % 3, bd = n % 3;
            const int x = t / 9, y = (t / 3) % 3, z = t % 3;
            const float val = __ldcg(&g_out0[(3 * bh + x) * 81 + (3 * bv + y) * 9 + (3 * bd + z)]);
            float cv, sv;
            sincosf(PI_HALF * val, &sv, &cv);
            sc[t] = cv; ss[t] = sv;
        }
        __syncwarp();

        const float u1 = half_bwd(gm1, l1l + n * 64, sc, ss, t);
        g_uR1[n * 32 + t] = u1;
        __threadfence();
        if (t == 0) atomicAdd(&g_half1[n], 1u);
        return;
    }

    // ---------- Layer 0 forward half + combine ----------
    float v = half_fwd(gm0, l0f + n * 64, sc, ss, t);
    spin_until(&g_half0[n], 1u);
    {
        const float uR = __ldcg(&g_uR0[n * 32 + t]);
        const float r = warp_sum(v * uR);
        if (t == 0) {
            g_out0[n] = r;
            __threadfence();
            const int X = n / 81, Y = (n / 9) % 9, Z = n % 9;
            atomicAdd(&g_grp[(X / 3) * 9 + (Y / 3) * 3 + (Z / 3)], 1u);
        }
    }
    if (n >= 27) return;

    // ---------- Layer 1 forward half + combine (chains 0..26) ----------
    const float* gm1 = l1m + n * (25 * STAGE_FLOATS);
    for (int i = t; i < FWD_STAGES * STAGE_FLOATS / 32; i += 32)
        l2_prefetch_line(gm1 + i * 32);
    if (n == 0) {                                 // final-layer weights too
        for (int i = t; i < 25 * STAGE_FLOATS / 32; i += 32)
            l2_prefetch_line(fm + i * 32);
    }
    spin_until(&g_grp[n], 27u);

    __syncwarp();
    if (t < 27) {
        const int bh = n / 9, bv = (n / 3) % 3, bd = n % 3;
        const int x = t / 9, y = (t / 3) % 3, z = t % 3;
        const float val = __ldcg(&g_out0[(3 * bh + x) * 81 + (3 * bv + y) * 9 + (3 * bd + z)]);
        float cv, sv;
        sincosf(PI_HALF * val, &sv, &cv);
        sc[t] = cv; ss[t] = sv;
    }
    __syncwarp();

    v = half_fwd(gm1, l1f + n * 64, sc, ss, t);
    spin_until(&g_half1[n], 1u);
    {
        const float uR = __ldcg(&g_uR1[n * 32 + t]);
        const float r = warp_sum(v * uR);
        if (t == 0) {
            g_out1[n] = r;
            __threadfence();
            atomicAdd(&g_ctr1, 1u);
        }
    }
    if (n != 0) return;

    // ---------- Final layer (block 0): full backward chain from L2 ----------
    spin_until(&g_ctr1, 27u);

    __syncwarp();
    if (t < 27) {
        // (3,3,3) squeeze of g_out1 is the identity permutation
        float cv, sv;
        sincosf(PI_HALF * __ldcg(&g_out1[t]), &sv, &cv);
        sc[t] = cv; ss[t] = sv;
    }
    __syncwarp();

    float u = fmaf(fl[2 * t], sc[26], fl[2 * t + 1] * ss[26]);
#pragma unroll 1
    for (int m = 24; m >= 0; m--)
        u = step_bwd(fm + m * STAGE_FLOATS, u, t, sc[m + 1], ss[m + 1]);

#pragma unroll
    for (int o = 0; o < 10; o++) {
        float p = fmaf(ff[o * 32 + t], sc[0], ff[320 + o * 32 + t] * ss[0]) * u;
        p = warp_sum(p);
        if (t == 0) out[o] = p;
    }
}

extern "C" void kernel_launch(void* const* d_in, const int* in_sizes, int n_in,
                              void* d_out, int out_size)
{
    const float* img      = (const float*)d_in[0];
    const float* l0_first = (const float*)d_in[1];
    const float* l0_mid   = (const float*)d_in[2];
    const float* l0_last  = (const float*)d_in[3];
    const float* l1_first = (const float*)d_in[4];
    const float* l1_mid   = (const float*)d_in[5];
    const float* l1_last  = (const float*)d_in[6];
    const float* f_first  = (const float*)d_in[7];
    const float* f_mid    = (const float*)d_in[8];
    const float* f_last   = (const float*)d_in[9];
    float* out = (float*)d_out;

    reset_kernel<<<1, 1024>>>();
    fused_kernel<<<1458, 32>>>(img, l0_first, l0_mid, l0_last,
                               l1_first, l1_mid, l1_last,
                               f_first, f_mid, f_last, out);
}

// round 11
// speedup vs baseline: 1.4425x; 1.0917x over previous
#include <cuda_runtime.h>
#include <cuda_bf16.h>
#include <math.h>
#include <stdint.h>

// Inter-layer scratch + sync (allocation-free rule: __device__ globals).
__device__ float g_out0[729];
__device__ float g_out1[27];
__device__ float g_uR1[27 * 32];     // layer1 backward half-results
__device__ unsigned g_grp[27];       // per-layer1-chain producer counters
__device__ unsigned g_half1[27];     // layer1 backward-half done flags
__device__ unsigned g_ctr1;          // layer1 completion counter

#define PI_HALF 1.57079632679489662f
#define STAGE_FLOATS 2048
#define FWD_STAGES 13                 // layer1 fwd: stages 0..12; bwd: 24..13

// ---------------- helpers ----------------
__device__ __forceinline__ float warp_sum(float v) {
#pragma unroll
    for (int o = 16; o > 0; o >>= 1)
        v += __shfl_down_sync(0xffffffffu, v, o);
    return v;
}
__device__ __forceinline__ void l2_prefetch_line(const float* p) {
    asm volatile("prefetch.global.L2 [%0];" :: "l"(p));
}
__device__ __forceinline__ void spin_until(const unsigned* c, unsigned target) {
    unsigned v;
    do {
        asm volatile("ld.global.acquire.gpu.u32 %0, [%1];"
                     : "=r"(v) : "l"(c) : "memory");
        if (v >= target) return;
        __nanosleep(128);
    } while (true);
}
// Prefetch one full 8 KB stage (64 lines) with 2 instructions per lane.
__device__ __forceinline__ void prefetch_stage(const float* g, int t) {
    l2_prefetch_line(g + t * 32);
    l2_prefetch_line(g + 1024 + t * 32);
}

// R1-proven forward chain loop (smem bond vector, coalesced column LDGs),
// plus one-stage-ahead L2 prefetch. Runs nst stages starting at mid.
// vbuf must contain v0 on entry; holds the result vector on exit.
__device__ __forceinline__ void chain_run(const float* __restrict__ mid, int nst,
                                          const float* sc1, const float* ss1,
                                          float* vbuf, int t)
{
#pragma unroll 1
    for (int m = 0; m < nst; m++) {
        if (m + 1 < nst) prefetch_stage(mid + (m + 1) * STAGE_FLOATS, t);
        const float* __restrict__ A = mid + m * STAGE_FLOATS;
        const float c = sc1[m], s = ss1[m];
        float acc = 0.0f;
#pragma unroll
        for (int d = 0; d < 32; d++)
            acc = fmaf(vbuf[d], fmaf(A[d * 64 + t], c, A[d * 64 + 32 + t] * s), acc);
        __syncwarp();
        vbuf[t] = acc;
        __syncwarp();
    }
}

// Backward step with per-lane contiguous row loads (only used on L2-warm data,
// and with few warps alive, so the 32-wavefront cost is irrelevant).
__device__ __forceinline__ float step_bwd(const float* __restrict__ g, float u,
                                          int t, float c, float s) {
    const float4* __restrict__ rp = (const float4*)(g + t * 64);
    float4 q[16];
#pragma unroll
    for (int i = 0; i < 16; i++) q[i] = rp[i];
    float acc0 = 0.0f, acc1 = 0.0f;
#pragma unroll
    for (int i = 0; i < 8; i++) {
        const float4 a = q[i];       // A[t][0][4i..4i+3]
        const float4 b = q[8 + i];   // A[t][1][4i..4i+3]
        float ue;
        ue = __shfl_sync(0xffffffffu, u, 4 * i + 0);
        acc0 = fmaf(a.x, ue, acc0);  acc1 = fmaf(b.x, ue, acc1);
        ue = __shfl_sync(0xffffffffu, u, 4 * i + 1);
        acc0 = fmaf(a.y, ue, acc0);  acc1 = fmaf(b.y, ue, acc1);
        ue = __shfl_sync(0xffffffffu, u, 4 * i + 2);
        acc0 = fmaf(a.z, ue, acc0);  acc1 = fmaf(b.z, ue, acc1);
        ue = __shfl_sync(0xffffffffu, u, 4 * i + 3);
        acc0 = fmaf(a.w, ue, acc0);  acc1 = fmaf(b.w, ue, acc1);
    }
    return fmaf(acc0, c, acc1 * s);
}

__global__ void reset_kernel() {
    const int i = threadIdx.x;
    if (i < 27) { g_grp[i] = 0; g_half1[i] = 0; }
    if (i == 27) g_ctr1 = 0;
}

// 729 blocks x 32 threads, one wave.
//  all blocks : layer0 chain n = blockIdx.x
//  n <  27    : layer1 forward half of chain n + combine (+ final for n==0)
//  27<=n<54   : layer1 backward half of chain n-27
__global__ void __launch_bounds__(32)
fused_kernel(const float* __restrict__ img,
             const float* __restrict__ l0f, const float* __restrict__ l0m,
             const float* __restrict__ l0l,
             const float* __restrict__ l1f, const float* __restrict__ l1m,
             const float* __restrict__ l1l,
             const float* __restrict__ ff,  const float* __restrict__ fm,
             const float* __restrict__ fl,
             float* __restrict__ out)
{
    __shared__ float sc[27], ss[27], vbuf[32];
    const int n = blockIdx.x;
    const int t = threadIdx.x;

    // ---------- Layer 0 ----------
    const float* gm0 = l0m + (long)n * (25 * STAGE_FLOATS);
    prefetch_stage(gm0, t);                       // stage 0 in flight during embed

    if (t < 27) {
        const int bh = n / 81, bv = (n / 9) % 9, bd = n % 9;
        const int x = t / 9, y = (t / 3) % 3, z = t % 3;
        const float val = img[(3 * bh + x) * 729 + (3 * bv + y) * 27 + (3 * bd + z)];
        float cv, sv;
        sincosf(PI_HALF * val, &sv, &cv);
        sc[t] = cv; ss[t] = sv;
    }
    __syncwarp();

    {
        const float* f0 = l0f + n * 64;
        vbuf[t] = fmaf(f0[t], sc[0], f0[32 + t] * ss[0]);
    }
    __syncwarp();
    chain_run(gm0, 25, sc + 1, ss + 1, vbuf, t);
    {
        const float* ln = l0l + n * 64;
        const float pv = vbuf[t] * fmaf(ln[2 * t], sc[26], ln[2 * t + 1] * ss[26]);
        const float r = warp_sum(pv);
        if (t == 0) {
            g_out0[n] = r;
            __threadfence();
            const int X = n / 81, Y = (n / 9) % 9, Z = n % 9;
            atomicAdd(&g_grp[(X / 3) * 9 + (Y / 3) * 3 + (Z / 3)], 1u);
        }
    }
    if (n >= 54) return;

    if (n >= 27) {
        // ---------- Layer 1 backward half (blocks 27..53, chain cidx) ----------
        const int cidx = n - 27;
        const float* gm1 = l1m + cidx * (25 * STAGE_FLOATS);
        // L2-warm my 12 stages before spinning.
        for (int i = t; i < (25 - FWD_STAGES) * 64; i += 32)
            l2_prefetch_line(gm1 + FWD_STAGES * STAGE_FLOATS + i * 32);
        spin_until(&g_grp[cidx], 27u);

        __syncwarp();
        if (t < 27) {
            const int bh = cidx / 9, bv = (cidx / 3) % 3, bd = cidx % 3;
            const int x = t / 9, y = (t / 3) % 3, z = t % 3;
            const float val = __ldcg(&g_out0[(3 * bh + x) * 81 + (3 * bv + y) * 9 + (3 * bd + z)]);
            float cv, sv;
            sincosf(PI_HALF * val, &sv, &cv);
            sc[t] = cv; ss[t] = sv;
        }
        __syncwarp();

        const float* l1 = l1l + cidx * 64;
        float u = fmaf(l1[2 * t], sc[26], l1[2 * t + 1] * ss[26]);
#pragma unroll 1
        for (int m = 24; m >= FWD_STAGES; m--)
            u = step_bwd(gm1 + m * STAGE_FLOATS, u, t, sc[m + 1], ss[m + 1]);
        g_uR1[cidx * 32 + t] = u;
        __threadfence();
        if (t == 0) atomicAdd(&g_half1[cidx], 1u);
        return;
    }

    // ---------- Layer 1 forward half (blocks 0..26) ----------
    const float* gm1 = l1m + n * (25 * STAGE_FLOATS);
    for (int i = t; i < FWD_STAGES * 64; i += 32)
        l2_prefetch_line(gm1 + i * 32);
    if (n == 0) {                                 // final-layer weights too
        for (int i = t; i < 25 * 64; i += 32)
            l2_prefetch_line(fm + i * 32);
    }
    spin_until(&g_grp[n], 27u);

    __syncwarp();
    if (t < 27) {
        const int bh = n / 9, bv = (n / 3) % 3, bd = n % 3;
        const int x = t / 9, y = (t / 3) % 3, z = t % 3;
        const float val = __ldcg(&g_out0[(3 * bh + x) * 81 + (3 * bv + y) * 9 + (3 * bd + z)]);
        float cv, sv;
        sincosf(PI_HALF * val, &sv, &cv);
        sc[t] = cv; ss[t] = sv;
    }
    __syncwarp();

    {
        const float* f1 = l1f + n * 64;
        vbuf[t] = fmaf(f1[t], sc[0], f1[32 + t] * ss[0]);
    }
    __syncwarp();
    chain_run(gm1, FWD_STAGES, sc + 1, ss + 1, vbuf, t);

    spin_until(&g_half1[n], 1u);
    {
        const float uR = __ldcg(&g_uR1[n * 32 + t]);
        const float r = warp_sum(vbuf[t] * uR);
        if (t == 0) {
            g_out1[n] = r;
            __threadfence();
            atomicAdd(&g_ctr1, 1u);
        }
    }
    if (n != 0) return;

    // ---------- Final layer (block 0): full backward chain (L2-warm) ----------
    spin_until(&g_ctr1, 27u);

    __syncwarp();
    if (t < 27) {
        // (3,3,3) squeeze of g_out1 is the identity permutation
        float cv, sv;
        sincosf(PI_HALF * __ldcg(&g_out1[t]), &sv, &cv);
        sc[t] = cv; ss[t] = sv;
    }
    __syncwarp();

    float u = fmaf(fl[2 * t], sc[26], fl[2 * t + 1] * ss[26]);
#pragma unroll 1
    for (int m = 24; m >= 0; m--)
        u = step_bwd(fm + m * STAGE_FLOATS, u, t, sc[m + 1], ss[m + 1]);

#pragma unroll
    for (int o = 0; o < 10; o++) {
        float p = fmaf(ff[o * 32 + t], sc[0], ff[320 + o * 32 + t] * ss[0]) * u;
        p = warp_sum(p);
        if (t == 0) out[o] = p;
    }
}

extern "C" void kernel_launch(void* const* d_in, const int* in_sizes, int n_in,
                              void* d_out, int out_size)
{
    const float* img      = (const float*)d_in[0];
    const float* l0_first = (const float*)d_in[1];
    const float* l0_mid   = (const float*)d_in[2];
    const float* l0_last  = (const float*)d_in[3];
    const float* l1_first = (const float*)d_in[4];
    const float* l1_mid   = (const float*)d_in[5];
    const float* l1_last  = (const float*)d_in[6];
    const float* f_first  = (const float*)d_in[7];
    const float* f_mid    = (const float*)d_in[8];
    const float* f_last   = (const float*)d_in[9];
    float* out = (float*)d_out;

    reset_kernel<<<1, 32>>>();
    fused_kernel<<<729, 32>>>(img, l0_first, l0_mid, l0_last,
                              l1_first, l1_mid, l1_last,
                              f_first, f_mid, f_last, out);
}